// round 1
// baseline (speedup 1.0000x reference)
#include <cuda_runtime.h>
#include <cstdint>

// Problem constants
#define B 128
#define T 512
#define I 50
#define H 256
#define PITCH 196           // smem pitch in floats for W rows (4t mod 32 bank pattern, conflict-free in 4 phases)
#define K_SMEM 192          // k-range of W kept in shared memory
#define K_REG  64           // k-range of W kept in registers (16 float4 per thread)

// Scratch: xp[dir][t][b][h]  (fp32), 2*512*128*256 floats = 134 MB
__device__ float g_xp[2u * T * B * H];

// ---------------------------------------------------------------------------
// Kernel 1: input projection. xp[d][t][b][h] = sum_i x[b][t_src][i]*w_ih_d[h][i] + b_ih_d[h] + b_hh_d[h]
// t_src = t for forward, T-1-t for backward.
// grid: (T, 2), block: 256 (thread = h)
// ---------------------------------------------------------------------------
__global__ __launch_bounds__(256) void proj_kernel(
    const float* __restrict__ x,
    const float* __restrict__ w_ih_f, const float* __restrict__ b_ih_f, const float* __restrict__ b_hh_f,
    const float* __restrict__ w_ih_b, const float* __restrict__ b_ih_b, const float* __restrict__ b_hh_b)
{
    __shared__ float xs[B * I];   // 25.6 KB

    const int t   = blockIdx.x;
    const int dir = blockIdx.y;
    const int h   = threadIdx.x;
    const int t_src = dir ? (T - 1 - t) : t;

    // stage x[:, t_src, :] into smem (coalesced enough; one-time per block)
    for (int idx = threadIdx.x; idx < B * I; idx += blockDim.x) {
        int b = idx / I;
        int i = idx - b * I;
        xs[idx] = x[((size_t)b * T + t_src) * I + i];
    }

    const float* w = dir ? w_ih_b : w_ih_f;
    // per-thread weight row as float2 (rows are 200B, 8-byte aligned)
    float2 wr[25];
    {
        const float2* w2 = reinterpret_cast<const float2*>(w + (size_t)h * I);
        #pragma unroll
        for (int i = 0; i < 25; i++) wr[i] = w2[i];
    }
    const float bias = dir ? (b_ih_b[h] + b_hh_b[h]) : (b_ih_f[h] + b_hh_f[h]);

    __syncthreads();

    float* xp_out = g_xp + (((size_t)dir * T + t) * B) * H + h;
    #pragma unroll 2
    for (int b = 0; b < B; b++) {
        const float2* xb = reinterpret_cast<const float2*>(&xs[b * I]);
        float acc0 = bias, acc1 = 0.f;
        #pragma unroll
        for (int i = 0; i < 25; i += 2) {
            float2 xv = xb[i];
            acc0 = fmaf(xv.x, wr[i].x, acc0);
            acc1 = fmaf(xv.y, wr[i].y, acc1);
            if (i + 1 < 25) {
                float2 xv2 = xb[i + 1];
                acc0 = fmaf(xv2.x, wr[i + 1].x, acc0);
                acc1 = fmaf(xv2.y, wr[i + 1].y, acc1);
            }
        }
        xp_out[(size_t)b * H] = acc0 + acc1;
    }
}

// ---------------------------------------------------------------------------
// Kernel 2: recurrence. 128 CTAs: blockIdx/64 = direction, each CTA owns 2 batch rows.
// Thread t owns output neuron n=t. W row: k in [0,192) from SMEM (pitch 196), k in [192,256) in regs.
// h double-buffered in SMEM, 1 barrier per step, xp prefetched 1 step ahead.
// out[b][time][dir*256 + n], fp32.
// ---------------------------------------------------------------------------
__global__ __launch_bounds__(256, 1) void rnn_kernel(
    const float* __restrict__ w_hh_f,
    const float* __restrict__ w_hh_b,
    float* __restrict__ out)
{
    extern __shared__ float sm[];
    float* Wsh = sm;                       // [256][PITCH]
    float* hs  = sm + 256 * PITCH;         // [2 buf][2 rows][256]

    const int dir = blockIdx.x >> 6;
    const int j   = blockIdx.x & 63;
    const int b0  = 2 * j;
    const int t   = threadIdx.x;

    const float* __restrict__ W = dir ? w_hh_b : w_hh_f;

    // Load W[:, 0:192] into smem
    for (int idx = t; idx < 256 * K_SMEM; idx += 256) {
        int n = idx / K_SMEM;
        int k = idx - n * K_SMEM;
        Wsh[n * PITCH + k] = W[n * H + k];
    }
    // Load W[t, 192:256] into regs
    float4 wreg[16];
    {
        const float4* wrow = reinterpret_cast<const float4*>(W + (size_t)t * H + K_SMEM);
        #pragma unroll
        for (int r = 0; r < 16; r++) wreg[r] = wrow[r];
    }
    // h0 = 0
    hs[0 * 512 + 0 * 256 + t] = 0.f;
    hs[0 * 512 + 1 * 256 + t] = 0.f;
    __syncthreads();

    const float* xp0 = g_xp + ((size_t)dir * T * B + b0) * H + t;       // xp[dir][s][b0][t]
    const float* xp1 = xp0 + H;                                          // b0+1
    const size_t step_stride = (size_t)B * H;                            // 32768 floats per s

    float xa = __ldg(xp0);
    float xb = __ldg(xp1);

    float* out_t = out + (size_t)dir * H + t;   // + ((b*T + time)*2H)

    int buf = 0;
    for (int s = 0; s < T; s++) {
        // prefetch next step's xp
        float nxa = 0.f, nxb = 0.f;
        if (s < T - 1) {
            nxa = __ldg(xp0 + (size_t)(s + 1) * step_stride);
            nxb = __ldg(xp1 + (size_t)(s + 1) * step_stride);
        }

        const float4* hv0 = reinterpret_cast<const float4*>(hs + buf * 512);
        const float4* hv1 = reinterpret_cast<const float4*>(hs + buf * 512 + 256);
        const float4* wv  = reinterpret_cast<const float4*>(Wsh + t * PITCH);

        float acc0 = xa, acc1 = xb;
        #pragma unroll
        for (int k4 = 0; k4 < K_SMEM / 4; k4++) {
            float4 w = wv[k4];
            float4 a = hv0[k4];
            float4 b = hv1[k4];
            acc0 = fmaf(w.x, a.x, acc0);  acc1 = fmaf(w.x, b.x, acc1);
            acc0 = fmaf(w.y, a.y, acc0);  acc1 = fmaf(w.y, b.y, acc1);
            acc0 = fmaf(w.z, a.z, acc0);  acc1 = fmaf(w.z, b.z, acc1);
            acc0 = fmaf(w.w, a.w, acc0);  acc1 = fmaf(w.w, b.w, acc1);
        }
        #pragma unroll
        for (int r = 0; r < 16; r++) {
            float4 w = wreg[r];
            float4 a = hv0[K_SMEM / 4 + r];
            float4 b = hv1[K_SMEM / 4 + r];
            acc0 = fmaf(w.x, a.x, acc0);  acc1 = fmaf(w.x, b.x, acc1);
            acc0 = fmaf(w.y, a.y, acc0);  acc1 = fmaf(w.y, b.y, acc1);
            acc0 = fmaf(w.z, a.z, acc0);  acc1 = fmaf(w.z, b.z, acc1);
            acc0 = fmaf(w.w, a.w, acc0);  acc1 = fmaf(w.w, b.w, acc1);
        }

        float h0 = fmaxf(acc0, 0.f);
        float h1 = fmaxf(acc1, 0.f);

        // output: forward -> time s, backward -> time T-1-s (re-reversal)
        const int time = dir ? (T - 1 - s) : s;
        out_t[((size_t)b0 * T + time) * (2 * H)] = h0;
        out_t[((size_t)(b0 + 1) * T + time) * (2 * H)] = h1;

        const int nb = buf ^ 1;
        hs[nb * 512 + t]       = h0;
        hs[nb * 512 + 256 + t] = h1;
        __syncthreads();

        buf = nb;
        xa = nxa;
        xb = nxb;
    }
}

// ---------------------------------------------------------------------------
extern "C" void kernel_launch(void* const* d_in, const int* in_sizes, int n_in,
                              void* d_out, int out_size)
{
    const float* x      = (const float*)d_in[0];
    const float* w_ih_f = (const float*)d_in[1];
    const float* w_hh_f = (const float*)d_in[2];
    const float* b_ih_f = (const float*)d_in[3];
    const float* b_hh_f = (const float*)d_in[4];
    const float* w_ih_b = (const float*)d_in[5];
    const float* w_hh_b = (const float*)d_in[6];
    const float* b_ih_b = (const float*)d_in[7];
    const float* b_hh_b = (const float*)d_in[8];
    float* out = (float*)d_out;

    static bool attr_set = false;
    const int smem_bytes = 256 * PITCH * 4 + 2 * 2 * 256 * 4;  // 200704 + 4096 = 204800
    if (!attr_set) {
        cudaFuncSetAttribute(rnn_kernel, cudaFuncAttributeMaxDynamicSharedMemorySize, smem_bytes);
        attr_set = true;
    }

    // 1) input projection for both directions
    proj_kernel<<<dim3(T, 2), 256>>>(x, w_ih_f, b_ih_f, b_hh_f, w_ih_b, b_ih_b, b_hh_b);

    // 2) recurrence: 128 CTAs (64 per direction, 2 batch rows each)
    rnn_kernel<<<128, 256, smem_bytes>>>(w_hh_f, w_hh_b, out);
}

// round 2
// speedup vs baseline: 1.2865x; 1.2865x over previous
#include <cuda_runtime.h>
#include <cstdint>

// Problem constants
#define B 128
#define T 512
#define I 50
#define H 256
#define K_SMEM 96           // k-range of W kept in shared memory
#define K_REG  160          // k-range of W kept in registers
#define PITCH 100           // smem pitch in floats (100 mod 32 == 4 -> conflict-free LDS.128)

// Scratch: xp[dir][t][b][h]  (fp32), 2*512*128*256 floats = 134 MB
__device__ float g_xp[2u * T * B * H];

// ---------------------------------------------------------------------------
// packed fp32x2 helpers (Blackwell)
// ---------------------------------------------------------------------------
__device__ __forceinline__ unsigned long long ffma2(unsigned long long a,
                                                    unsigned long long b,
                                                    unsigned long long c) {
    unsigned long long d;
    asm("fma.rn.f32x2 %0, %1, %2, %3;" : "=l"(d) : "l"(a), "l"(b), "l"(c));
    return d;
}
__device__ __forceinline__ float2 u2f(unsigned long long v) {
    float2 f;
    asm("mov.b64 {%0, %1}, %2;" : "=f"(f.x), "=f"(f.y) : "l"(v));
    return f;
}

// ---------------------------------------------------------------------------
// Kernel 1: input projection. xp[d][t][b][h] = x[b][t_src] . w_ih_d[h] + b_ih_d[h] + b_hh_d[h]
// ---------------------------------------------------------------------------
__global__ __launch_bounds__(256) void proj_kernel(
    const float* __restrict__ x,
    const float* __restrict__ w_ih_f, const float* __restrict__ b_ih_f, const float* __restrict__ b_hh_f,
    const float* __restrict__ w_ih_b, const float* __restrict__ b_ih_b, const float* __restrict__ b_hh_b)
{
    __shared__ float xs[B * I];   // 25.6 KB

    const int t   = blockIdx.x;
    const int dir = blockIdx.y;
    const int h   = threadIdx.x;
    const int t_src = dir ? (T - 1 - t) : t;

    for (int idx = threadIdx.x; idx < B * I; idx += blockDim.x) {
        int b = idx / I;
        int i = idx - b * I;
        xs[idx] = x[((size_t)b * T + t_src) * I + i];
    }

    const float* w = dir ? w_ih_b : w_ih_f;
    float2 wr[25];
    {
        const float2* w2 = reinterpret_cast<const float2*>(w + (size_t)h * I);
        #pragma unroll
        for (int i = 0; i < 25; i++) wr[i] = w2[i];
    }
    const float bias = dir ? (b_ih_b[h] + b_hh_b[h]) : (b_ih_f[h] + b_hh_f[h]);

    __syncthreads();

    float* xp_out = g_xp + (((size_t)dir * T + t) * B) * H + h;
    #pragma unroll 2
    for (int b = 0; b < B; b++) {
        const float2* xb = reinterpret_cast<const float2*>(&xs[b * I]);
        float acc0 = bias, acc1 = 0.f;
        #pragma unroll
        for (int i = 0; i < 25; i++) {
            float2 xv = xb[i];
            acc0 = fmaf(xv.x, wr[i].x, acc0);
            acc1 = fmaf(xv.y, wr[i].y, acc1);
        }
        xp_out[(size_t)b * H] = acc0 + acc1;
    }
}

// ---------------------------------------------------------------------------
// Kernel 2: recurrence. 128 CTAs: blockIdx/64 = direction, 2 batch rows per CTA.
// Thread t owns neuron n=t. W[t, 0:96] from SMEM (pitch 100), W[t, 96:256] in regs.
// Dot products in packed fp32x2 (FFMA2), 4 independent chains per thread.
// h double-buffered in SMEM, one barrier per step, xp prefetched one step ahead.
// ---------------------------------------------------------------------------
__global__ __launch_bounds__(256, 1) void rnn_kernel(
    const float* __restrict__ w_hh_f,
    const float* __restrict__ w_hh_b,
    float* __restrict__ out)
{
    extern __shared__ float sm[];
    float* Wsh = sm;                       // [256][PITCH]  (102,400 B)
    float* hs  = sm + 256 * PITCH;         // [2 buf][2 rows][256]  (4,096 B)

    const int dir = blockIdx.x >> 6;
    const int j   = blockIdx.x & 63;
    const int b0  = 2 * j;
    const int t   = threadIdx.x;

    const float* __restrict__ W = dir ? w_hh_b : w_hh_f;

    // W[:, 0:K_SMEM] -> smem
    for (int idx = t; idx < 256 * K_SMEM; idx += 256) {
        int n = idx / K_SMEM;
        int k = idx - n * K_SMEM;
        Wsh[n * PITCH + k] = W[n * H + k];
    }
    // W[t, K_SMEM:256] -> regs, as packed (k,k+1) pairs
    ulonglong2 wreg[K_REG / 4];            // 40 x 16B = 160 floats
    {
        const ulonglong2* wrow = reinterpret_cast<const ulonglong2*>(W + (size_t)t * H + K_SMEM);
        #pragma unroll
        for (int r = 0; r < K_REG / 4; r++) wreg[r] = wrow[r];
    }
    hs[0 * 512 + 0 * 256 + t] = 0.f;
    hs[0 * 512 + 1 * 256 + t] = 0.f;
    __syncthreads();

    const float* xp0 = g_xp + ((size_t)dir * T * B + b0) * H + t;
    const float* xp1 = xp0 + H;
    const size_t step_stride = (size_t)B * H;

    float xa = __ldg(xp0);
    float xb = __ldg(xp1);

    float* out_t = out + (size_t)dir * H + t;

    int buf = 0;
    for (int s = 0; s < T; s++) {
        float nxa = 0.f, nxb = 0.f;
        if (s < T - 1) {
            nxa = __ldg(xp0 + (size_t)(s + 1) * step_stride);
            nxb = __ldg(xp1 + (size_t)(s + 1) * step_stride);
        }

        const ulonglong2* h0v = reinterpret_cast<const ulonglong2*>(hs + buf * 512);
        const ulonglong2* h1v = reinterpret_cast<const ulonglong2*>(hs + buf * 512 + 256);
        const ulonglong2* wv  = reinterpret_cast<const ulonglong2*>(Wsh + t * PITCH);

        // 4 independent packed accumulator chains (2 per batch row)
        unsigned long long aA0 = 0ull, aB0 = 0ull, aA1 = 0ull, aB1 = 0ull;

        // k in [0, K_SMEM): W from shared
        #pragma unroll
        for (int i = 0; i < K_SMEM / 4; i++) {
            ulonglong2 w  = wv[i];
            ulonglong2 ha = h0v[i];
            ulonglong2 hb = h1v[i];
            aA0 = ffma2(w.x, ha.x, aA0);
            aB0 = ffma2(w.y, ha.y, aB0);
            aA1 = ffma2(w.x, hb.x, aA1);
            aB1 = ffma2(w.y, hb.y, aB1);
        }
        // k in [K_SMEM, 256): W from regs
        #pragma unroll
        for (int r = 0; r < K_REG / 4; r++) {
            ulonglong2 w  = wreg[r];
            ulonglong2 ha = h0v[K_SMEM / 4 + r];
            ulonglong2 hb = h1v[K_SMEM / 4 + r];
            aA0 = ffma2(w.x, ha.x, aA0);
            aB0 = ffma2(w.y, ha.y, aB0);
            aA1 = ffma2(w.x, hb.x, aA1);
            aB1 = ffma2(w.y, hb.y, aB1);
        }

        float2 fA0 = u2f(aA0), fB0 = u2f(aB0);
        float2 fA1 = u2f(aA1), fB1 = u2f(aB1);
        float h0 = fmaxf(xa + ((fA0.x + fA0.y) + (fB0.x + fB0.y)), 0.f);
        float h1 = fmaxf(xb + ((fA1.x + fA1.y) + (fB1.x + fB1.y)), 0.f);

        const int time = dir ? (T - 1 - s) : s;
        out_t[((size_t)b0 * T + time) * (2 * H)] = h0;
        out_t[((size_t)(b0 + 1) * T + time) * (2 * H)] = h1;

        const int nb = buf ^ 1;
        hs[nb * 512 + t]       = h0;
        hs[nb * 512 + 256 + t] = h1;
        __syncthreads();

        buf = nb;
        xa = nxa;
        xb = nxb;
    }
}

// ---------------------------------------------------------------------------
extern "C" void kernel_launch(void* const* d_in, const int* in_sizes, int n_in,
                              void* d_out, int out_size)
{
    const float* x      = (const float*)d_in[0];
    const float* w_ih_f = (const float*)d_in[1];
    const float* w_hh_f = (const float*)d_in[2];
    const float* b_ih_f = (const float*)d_in[3];
    const float* b_hh_f = (const float*)d_in[4];
    const float* w_ih_b = (const float*)d_in[5];
    const float* w_hh_b = (const float*)d_in[6];
    const float* b_ih_b = (const float*)d_in[7];
    const float* b_hh_b = (const float*)d_in[8];
    float* out = (float*)d_out;

    static bool attr_set = false;
    const int smem_bytes = 256 * PITCH * 4 + 2 * 2 * 256 * 4;  // 102400 + 4096 = 106496
    if (!attr_set) {
        cudaFuncSetAttribute(rnn_kernel, cudaFuncAttributeMaxDynamicSharedMemorySize, smem_bytes);
        attr_set = true;
    }

    proj_kernel<<<dim3(T, 2), 256>>>(x, w_ih_f, b_ih_f, b_hh_f, w_ih_b, b_ih_b, b_hh_b);
    rnn_kernel<<<128, 256, smem_bytes>>>(w_hh_f, w_hh_b, out);
}